// round 4
// baseline (speedup 1.0000x reference)
#include <cuda_runtime.h>
#include <cstdint>

#define N_NODES 50000
#define N_EDGES 600000
#define HID     128
#define N_GRAPHS 32
#define D_OUT   3
#define SCAN_BLOCKS ((N_NODES + 255) / 256)   // 196

// ---------------- scratch (device globals; no allocs) ----------------
__device__ int   g_cnt[N_NODES];
__device__ int   g_rowptr[N_NODES + 1];
__device__ int   g_cursor[N_NODES];
__device__ int   g_col[N_EDGES];
__device__ int   g_bsum[SCAN_BLOCKS];
__device__ int   g_boff[SCAN_BLOCKS];
__device__ float g_aggr[(size_t)N_NODES * HID];
__device__ float g_bufA[(size_t)N_NODES * HID];
__device__ float g_bufB[(size_t)N_NODES * HID];
__device__ float g_gsum[N_GRAPHS * HID];
__device__ float g_gcnt[N_GRAPHS];

// ---------------- tf32 helpers ----------------
__device__ __forceinline__ uint32_t f2tf32(float f) {
    uint32_t u;
    asm("cvt.rna.tf32.f32 %0, %1;" : "=r"(u) : "f"(f));
    return u;
}
__device__ __forceinline__ void mma_tf32(float* c, uint32_t a0, uint32_t a1,
                                         uint32_t a2, uint32_t a3,
                                         uint32_t b0, uint32_t b1) {
    asm volatile(
        "mma.sync.aligned.m16n8k8.row.col.f32.tf32.tf32.f32 "
        "{%0,%1,%2,%3}, {%4,%5,%6,%7}, {%8,%9}, {%0,%1,%2,%3};"
        : "+f"(c[0]), "+f"(c[1]), "+f"(c[2]), "+f"(c[3])
        : "r"(a0), "r"(a1), "r"(a2), "r"(a3), "r"(b0), "r"(b1));
}

// smem: sA = fp32 [128 rows][128 k], float4-swizzled  (64KB)
//       sW = (hi,lo) tf32 pairs [128 n][128 k], float2-swizzled (128KB)
#define SMEM_GEMM (65536 + 131072)

// ---------------- persistent tf32-MMA GEMM ----------------
// out[M,128] = act( A[M,128] @ W[128,128]^T (+bias) (+accum) )
__global__ void __launch_bounds__(256, 1)
gemm_mma(const float* __restrict__ A, const float* __restrict__ W,
         const float* __restrict__ bias, const float* __restrict__ accum,
         float* __restrict__ out, int M, int do_relu, int has_bias) {
    extern __shared__ char smem[];
    float*  sA = (float*)smem;
    float2* sW = (float2*)(smem + 65536);

    int tid = threadIdx.x, lane = tid & 31, wid = tid >> 5;

    // ---- stage W as (hi, lo) tf32 pairs, swizzled: idx = n*128 + (k ^ ((n&3)<<2))
    for (int i = tid; i < 16384; i += 256) {
        int n = i >> 7, k = i & 127;
        float w = W[n * 128 + k];
        uint32_t hi = f2tf32(w);
        uint32_t lo = f2tf32(w - __uint_as_float(hi));
        sW[n * 128 + (k ^ ((n & 3) << 2))] =
            make_float2(__uint_as_float(hi), __uint_as_float(lo));
    }

    const float4* A4 = (const float4*)A;
    int r7 = lane >> 2;          // row & 7 for this lane's A-frag rows
    int mrow = wid * 16 + r7;    // first frag row within tile

    int ntiles = (M + 127) >> 7;
    for (int t = blockIdx.x; t < ntiles; t += gridDim.x) {
        int m0 = t << 7;
        __syncthreads();   // protect sA from previous tile's readers
        // ---- stage A fp32, swizzled in float4 units: idx4 = row*32 + (c4 ^ (row&7))
        for (int i = tid; i < 4096; i += 256) {
            int row = i >> 5, c4 = i & 31;
            int grow = m0 + row;
            float4 a = make_float4(0.f, 0.f, 0.f, 0.f);
            if (grow < M) a = A4[(size_t)grow * 32 + c4];
            *(float4*)(sA + row * 128 + ((c4 ^ (row & 7)) << 2)) = a;
        }
        __syncthreads();

        float acc[16][4];
        #pragma unroll
        for (int n = 0; n < 16; n++)
            #pragma unroll
            for (int j = 0; j < 4; j++) acc[n][j] = 0.f;

        #pragma unroll 1
        for (int ks = 0; ks < 16; ks++) {
            int k0 = ks * 8;
            int kc = k0 + (lane & 3);
            // A frags (fp32 from smem, split to tf32 hi/lo in regs)
            float af0 = sA[mrow * 128 + (kc ^ (r7 << 2))];
            float af1 = sA[(mrow + 8) * 128 + (kc ^ (r7 << 2))];
            float af2 = sA[mrow * 128 + ((kc + 4) ^ (r7 << 2))];
            float af3 = sA[(mrow + 8) * 128 + ((kc + 4) ^ (r7 << 2))];
            uint32_t ah0 = f2tf32(af0), ah1 = f2tf32(af1);
            uint32_t ah2 = f2tf32(af2), ah3 = f2tf32(af3);
            uint32_t al0 = f2tf32(af0 - __uint_as_float(ah0));
            uint32_t al1 = f2tf32(af1 - __uint_as_float(ah1));
            uint32_t al2 = f2tf32(af2 - __uint_as_float(ah2));
            uint32_t al3 = f2tf32(af3 - __uint_as_float(ah3));

            #pragma unroll
            for (int n = 0; n < 16; n++) {
                int nn = n * 8 + (lane >> 2);
                int sw = (nn & 3) << 2;
                float2 p0 = sW[nn * 128 + (kc ^ sw)];
                float2 p1 = sW[nn * 128 + ((kc + 4) ^ sw)];
                uint32_t bh0 = __float_as_uint(p0.x), bl0 = __float_as_uint(p0.y);
                uint32_t bh1 = __float_as_uint(p1.x), bl1 = __float_as_uint(p1.y);
                mma_tf32(acc[n], ah0, ah1, ah2, ah3, bh0, bh1);
                mma_tf32(acc[n], ah0, ah1, ah2, ah3, bl0, bl1);
                mma_tf32(acc[n], al0, al1, al2, al3, bh0, bh1);
            }
        }

        // ---- epilogue: c0/c1 -> (row, col..col+1), c2/c3 -> (row+8, ...)
        int row0 = m0 + wid * 16 + (lane >> 2);
        #pragma unroll
        for (int n = 0; n < 16; n++) {
            int col = n * 8 + (lane & 3) * 2;
            float o0 = acc[n][0], o1 = acc[n][1];
            float o2 = acc[n][2], o3 = acc[n][3];
            if (has_bias) {
                float2 b = *(const float2*)(bias + col);
                o0 += b.x; o1 += b.y; o2 += b.x; o3 += b.y;
            }
            if (row0 < M) {
                if (accum) {
                    float2 ac = *(const float2*)(accum + (size_t)row0 * 128 + col);
                    o0 += ac.x; o1 += ac.y;
                }
                if (do_relu) { o0 = fmaxf(o0, 0.f); o1 = fmaxf(o1, 0.f); }
                *(float2*)(out + (size_t)row0 * 128 + col) = make_float2(o0, o1);
            }
            if (row0 + 8 < M) {
                if (accum) {
                    float2 ac = *(const float2*)(accum + (size_t)(row0 + 8) * 128 + col);
                    o2 += ac.x; o3 += ac.y;
                }
                if (do_relu) { o2 = fmaxf(o2, 0.f); o3 = fmaxf(o3, 0.f); }
                *(float2*)(out + (size_t)(row0 + 8) * 128 + col) = make_float2(o2, o3);
            }
        }
    }
}

// ---------------- CSR build ----------------
__global__ void zero_kernel() {
    int i = blockIdx.x * blockDim.x + threadIdx.x;
    if (i < N_NODES) g_cnt[i] = 0;
    if (i < N_GRAPHS * HID) g_gsum[i] = 0.0f;
    if (i < N_GRAPHS) g_gcnt[i] = 0.0f;
}

__global__ void hist_kernel(const int* __restrict__ dst) {
    int e4 = blockIdx.x * blockDim.x + threadIdx.x;
    if (e4 < N_EDGES / 4) {
        int4 d = ((const int4*)dst)[e4];
        atomicAdd(&g_cnt[d.x], 1);
        atomicAdd(&g_cnt[d.y], 1);
        atomicAdd(&g_cnt[d.z], 1);
        atomicAdd(&g_cnt[d.w], 1);
    }
}

// two-level scan: block sums -> scan of sums -> per-block rescan
__global__ void scan1_kernel() {
    __shared__ int ws[8];
    int tid = threadIdx.x, lane = tid & 31, w = tid >> 5;
    int i = blockIdx.x * 256 + tid;
    int v = (i < N_NODES) ? g_cnt[i] : 0;
    #pragma unroll
    for (int off = 16; off > 0; off >>= 1)
        v += __shfl_down_sync(0xffffffffu, v, off);
    if (lane == 0) ws[w] = v;
    __syncthreads();
    if (tid == 0) {
        int s = 0;
        #pragma unroll
        for (int j = 0; j < 8; j++) s += ws[j];
        g_bsum[blockIdx.x] = s;
    }
}

__global__ void scan2_kernel() {
    __shared__ int ws[8];
    int tid = threadIdx.x, lane = tid & 31, w = tid >> 5;
    int v = (tid < SCAN_BLOCKS) ? g_bsum[tid] : 0;
    int x = v;
    #pragma unroll
    for (int off = 1; off < 32; off <<= 1) {
        int t = __shfl_up_sync(0xffffffffu, x, off);
        if (lane >= off) x += t;
    }
    if (lane == 31) ws[w] = x;
    __syncthreads();
    if (w == 0 && lane < 8) {
        int y = ws[lane];
        #pragma unroll
        for (int off = 1; off < 8; off <<= 1) {
            int t = __shfl_up_sync(0xffu, y, off);
            if (lane >= off) y += t;
        }
        ws[lane] = y;
    }
    __syncthreads();
    int incl = x + (w > 0 ? ws[w - 1] : 0);
    if (tid < SCAN_BLOCKS) g_boff[tid] = incl - v;   // exclusive
    if (tid == 0) g_rowptr[0] = 0;
}

__global__ void scan3_kernel() {
    __shared__ int ws[8];
    int tid = threadIdx.x, lane = tid & 31, w = tid >> 5;
    int i = blockIdx.x * 256 + tid;
    int v = (i < N_NODES) ? g_cnt[i] : 0;
    int x = v;
    #pragma unroll
    for (int off = 1; off < 32; off <<= 1) {
        int t = __shfl_up_sync(0xffffffffu, x, off);
        if (lane >= off) x += t;
    }
    if (lane == 31) ws[w] = x;
    __syncthreads();
    if (w == 0 && lane < 8) {
        int y = ws[lane];
        #pragma unroll
        for (int off = 1; off < 8; off <<= 1) {
            int t = __shfl_up_sync(0xffu, y, off);
            if (lane >= off) y += t;
        }
        ws[lane] = y;
    }
    __syncthreads();
    int incl = x + (w > 0 ? ws[w - 1] : 0) + g_boff[blockIdx.x];
    if (i < N_NODES) {
        g_rowptr[i + 1] = incl;
        g_cursor[i] = incl - v;
    }
}

__global__ void fill_kernel(const int* __restrict__ src,
                            const int* __restrict__ dst) {
    int e4 = blockIdx.x * blockDim.x + threadIdx.x;
    if (e4 < N_EDGES / 4) {
        int4 d = ((const int4*)dst)[e4];
        int4 s = ((const int4*)src)[e4];
        g_col[atomicAdd(&g_cursor[d.x], 1)] = s.x;
        g_col[atomicAdd(&g_cursor[d.y], 1)] = s.y;
        g_col[atomicAdd(&g_cursor[d.z], 1)] = s.z;
        g_col[atomicAdd(&g_cursor[d.w], 1)] = s.w;
    }
}

// ---------------- aggregation: warp per node, float4 per lane ----------------
__global__ void agg_kernel(const float* __restrict__ in, float* __restrict__ out) {
    int node = (blockIdx.x * blockDim.x + threadIdx.x) >> 5;
    int lane = threadIdx.x & 31;
    if (node >= N_NODES) return;
    int s = g_rowptr[node];
    int e = g_rowptr[node + 1];
    float4 acc = make_float4(0.f, 0.f, 0.f, 0.f);
    for (int j = s; j < e; j++) {
        int sn = g_col[j];
        float4 v = *(const float4*)(in + (size_t)sn * HID + lane * 4);
        acc.x += v.x; acc.y += v.y; acc.z += v.z; acc.w += v.w;
    }
    int deg = e - s;
    float inv = 1.0f / (float)(deg > 0 ? deg : 1);
    acc.x *= inv; acc.y *= inv; acc.z *= inv; acc.w *= inv;
    *(float4*)(out + (size_t)node * HID + lane * 4) = acc;
}

// ---------------- pooling (batch is sorted) ----------------
__global__ void pool_kernel(const float* __restrict__ h,
                            const int* __restrict__ batch) {
    int t = threadIdx.x;
    int r0 = blockIdx.x * 128;
    if (r0 >= N_NODES) return;
    int r1 = r0 + 128; if (r1 > N_NODES) r1 = N_NODES;
    int gprev = batch[r0];
    float acc = 0.0f;
    float cacc = 0.0f;
    for (int r = r0; r < r1; r++) {
        int g = batch[r];
        if (g != gprev) {
            atomicAdd(&g_gsum[gprev * HID + t], acc);
            if (t == 0) atomicAdd(&g_gcnt[gprev], cacc);
            acc = 0.0f; cacc = 0.0f; gprev = g;
        }
        acc += h[(size_t)r * HID + t];
        cacc += 1.0f;
    }
    atomicAdd(&g_gsum[gprev * HID + t], acc);
    if (t == 0) atomicAdd(&g_gcnt[gprev], cacc);
}

// ---------------- final: out[g][o] = mean_pool @ fc^T + fc_b ----------------
__global__ void final_kernel(const float* __restrict__ fcW,
                             const float* __restrict__ fcb,
                             float* __restrict__ out) {
    int t = threadIdx.x;
    if (t >= N_GRAPHS * D_OUT) return;
    int g = t / D_OUT, o = t % D_OUT;
    float cnt = g_gcnt[g];
    float inv = 1.0f / fmaxf(cnt, 1.0f);
    float s = 0.0f;
    #pragma unroll 8
    for (int k = 0; k < HID; k++)
        s += g_gsum[g * HID + k] * fcW[o * HID + k];
    out[g * D_OUT + o] = s * inv + fcb[o];
}

// ---------------- launch ----------------
extern "C" void kernel_launch(void* const* d_in, const int* in_sizes, int n_in,
                              void* d_out, int out_size) {
    const float* x    = (const float*)d_in[0];
    const float* Wl0  = (const float*)d_in[1];
    const float* bl0  = (const float*)d_in[2];
    const float* Wr0  = (const float*)d_in[3];
    const float* W1   = (const float*)d_in[4];
    const float* b1   = (const float*)d_in[5];
    const float* Wl1  = (const float*)d_in[6];
    const float* bl1  = (const float*)d_in[7];
    const float* Wr1  = (const float*)d_in[8];
    const float* fcW  = (const float*)d_in[9];
    const float* fcb  = (const float*)d_in[10];
    const int*   ei   = (const int*)d_in[11];     // int64 ref -> int32 harness
    const int*   batch= (const int*)d_in[12];
    float*       out  = (float*)d_out;

    const int* src = ei;
    const int* dst = ei + N_EDGES;

    void *pAg = nullptr, *pA = nullptr, *pB = nullptr;
    cudaGetSymbolAddress(&pAg, g_aggr);
    cudaGetSymbolAddress(&pA,  g_bufA);
    cudaGetSymbolAddress(&pB,  g_bufB);
    float* aggr = (float*)pAg;
    float* bufA = (float*)pA;
    float* bufB = (float*)pB;

    cudaFuncSetAttribute(gemm_mma, cudaFuncAttributeMaxDynamicSharedMemorySize, SMEM_GEMM);

    // CSR build
    zero_kernel<<<(N_NODES + 255) / 256, 256>>>();
    hist_kernel<<<(N_EDGES / 4 + 255) / 256, 256>>>(dst);
    scan1_kernel<<<SCAN_BLOCKS, 256>>>();
    scan2_kernel<<<1, 256>>>();
    scan3_kernel<<<SCAN_BLOCKS, 256>>>();
    fill_kernel<<<(N_EDGES / 4 + 255) / 256, 256>>>(src, dst);

    // conv0: bufA = relu( x@Wr0^T + bl0 + aggr(x)@Wl0^T )
    gemm_mma<<<148, 256, SMEM_GEMM>>>(x, Wr0, bl0, nullptr, bufA, N_NODES, 0, 1);
    agg_kernel<<<(N_NODES + 7) / 8, 256>>>(x, aggr);
    gemm_mma<<<148, 256, SMEM_GEMM>>>(aggr, Wl0, nullptr, bufA, bufA, N_NODES, 1, 0);

    // lin1: bufB = relu( bufA@W1^T + b1 )
    gemm_mma<<<148, 256, SMEM_GEMM>>>(bufA, W1, b1, nullptr, bufB, N_NODES, 1, 1);

    // conv1: bufA = relu( bufB@Wr1^T + bl1 + aggr(bufB)@Wl1^T )
    gemm_mma<<<148, 256, SMEM_GEMM>>>(bufB, Wr1, bl1, nullptr, bufA, N_NODES, 0, 1);
    agg_kernel<<<(N_NODES + 7) / 8, 256>>>(bufB, aggr);
    gemm_mma<<<148, 256, SMEM_GEMM>>>(aggr, Wl1, nullptr, bufA, bufA, N_NODES, 1, 0);

    // pool + fc
    pool_kernel<<<(N_NODES + 127) / 128, 128>>>(bufA, batch);
    final_kernel<<<1, 96>>>(fcW, fcb, out);
}

// round 5
// speedup vs baseline: 1.2303x; 1.2303x over previous
#include <cuda_runtime.h>
#include <cstdint>

#define N_NODES 50000
#define N_EDGES 600000
#define HID     128
#define N_GRAPHS 32
#define D_OUT   3
#define SCAN_BLOCKS ((N_NODES + 255) / 256)   // 196

typedef unsigned long long u64;

// ---------------- scratch (device globals; no allocs) ----------------
__device__ int   g_cnt[N_NODES];
__device__ int   g_rowptr[N_NODES + 1];
__device__ int   g_cursor[N_NODES];
__device__ int   g_col[N_EDGES];
__device__ int   g_bsum[SCAN_BLOCKS];
__device__ float g_aggr[(size_t)N_NODES * HID];   // P = x @ Wl^T
__device__ float g_bufA[(size_t)N_NODES * HID];
__device__ float g_bufB[(size_t)N_NODES * HID];
__device__ float g_gsum[N_GRAPHS * HID];
__device__ float g_gcnt[N_GRAPHS];

// ---------------- f32x2 helpers ----------------
__device__ __forceinline__ u64 pack_dup(float a) {
    u64 r;
    asm("mov.b64 %0, {%1,%1};" : "=l"(r) : "f"(a));
    return r;
}
__device__ __forceinline__ float2 unpack2(u64 v) {
    float2 r;
    asm("mov.b64 {%0,%1}, %2;" : "=f"(r.x), "=f"(r.y) : "l"(v));
    return r;
}
__device__ __forceinline__ void ffma2(u64& acc, u64 a, u64 b) {
    asm("fma.rn.f32x2 %0, %1, %2, %0;" : "+l"(acc) : "l"(a), "l"(b));
}

// =================================================================
// Dual-weight GEMM: out1 = A@W1^T + bias (relu opt), out2 = A@W2^T
// 128x128 block tile, 256 threads, 8x8 microtile, packed fma.rn.f32x2.
// A tile staged once, both weight products computed from it.
// =================================================================
template<int DUAL>
__global__ void __launch_bounds__(256, 1)
gemm_dw(const float* __restrict__ A,
        const float* __restrict__ W1, const float* __restrict__ W2,
        const float* __restrict__ bias,
        float* __restrict__ out1, float* __restrict__ out2,
        int M, int relu1) {
    extern __shared__ float smem[];
    float* sIn = smem;            // [row*128 + k]
    float* sW1 = smem + 16384;    // k-major, float4 XOR-swizzled along cols
    float* sW2 = smem + 32768;

    int tid = threadIdx.x;
    int tx = tid & 15;        // col group (8 cols)
    int ty = tid >> 4;        // row group (8 rows)
    int m0 = blockIdx.x * 128;
    int lane = tid & 31;
    int sub  = tid >> 5;      // 0..7

    // load input tile [128 rows x 128 k]
    #pragma unroll
    for (int it = 0; it < 16; it++) {
        int row = it * 8 + sub;
        int grow = m0 + row;
        float4 v = make_float4(0.f, 0.f, 0.f, 0.f);
        if (grow < M) v = *(const float4*)(A + (size_t)grow * 128 + lane * 4);
        *(float4*)(sIn + row * 128 + lane * 4) = v;
    }
    // load W transposed into k-major with float4 XOR swizzle:
    // logical (k, c4) lives at sW[k*128 + ((c4 ^ ((k>>2)&31))<<2)]
    #pragma unroll
    for (int it = 0; it < 16; it++) {
        int col = it * 8 + sub;
        float4 v1 = *(const float4*)(W1 + col * 128 + (lane << 2));
        int c4 = col >> 2;
        int cl = col & 3;
        float vv1[4] = {v1.x, v1.y, v1.z, v1.w};
        #pragma unroll
        for (int i = 0; i < 4; i++) {
            int k = (lane << 2) + i;     // (k>>2)&31 == lane
            sW1[k * 128 + ((c4 ^ lane) << 2) + cl] = vv1[i];
        }
        if (DUAL) {
            float4 v2 = *(const float4*)(W2 + col * 128 + (lane << 2));
            float vv2[4] = {v2.x, v2.y, v2.z, v2.w};
            #pragma unroll
            for (int i = 0; i < 4; i++) {
                int k = (lane << 2) + i;
                sW2[k * 128 + ((c4 ^ lane) << 2) + cl] = vv2[i];
            }
        }
    }
    __syncthreads();

    u64 acc1[8][4];
    u64 acc2[DUAL ? 8 : 1][4];
    #pragma unroll
    for (int r = 0; r < 8; r++)
        #pragma unroll
        for (int c = 0; c < 4; c++) acc1[r][c] = 0ull;
    #pragma unroll
    for (int r = 0; r < (DUAL ? 8 : 1); r++)
        #pragma unroll
        for (int c = 0; c < 4; c++) acc2[r][c] = 0ull;

    #pragma unroll 4
    for (int k = 0; k < 128; k++) {
        u64 a2[8];
        #pragma unroll
        for (int r = 0; r < 8; r++)
            a2[r] = pack_dup(sIn[(ty * 8 + r) * 128 + k]);
        int swz = (k >> 2) & 31;
        const float* w1r = sW1 + k * 128;
        ulonglong2 p0 = *(const ulonglong2*)(w1r + ((((tx << 1)    ) ^ swz) << 2));
        ulonglong2 p1 = *(const ulonglong2*)(w1r + ((((tx << 1) | 1) ^ swz) << 2));
        u64 b1[4] = {p0.x, p0.y, p1.x, p1.y};
        #pragma unroll
        for (int r = 0; r < 8; r++)
            #pragma unroll
            for (int c = 0; c < 4; c++)
                ffma2(acc1[r][c], a2[r], b1[c]);
        if (DUAL) {
            const float* w2r = sW2 + k * 128;
            ulonglong2 q0 = *(const ulonglong2*)(w2r + ((((tx << 1)    ) ^ swz) << 2));
            ulonglong2 q1 = *(const ulonglong2*)(w2r + ((((tx << 1) | 1) ^ swz) << 2));
            u64 b2[4] = {q0.x, q0.y, q1.x, q1.y};
            #pragma unroll
            for (int r = 0; r < 8; r++)
                #pragma unroll
                for (int c = 0; c < 4; c++)
                    ffma2(acc2[r][c], a2[r], b2[c]);
        }
    }

    // epilogue
    float bv[8];
    #pragma unroll
    for (int j = 0; j < 8; j++) bv[j] = bias[tx * 8 + j];

    #pragma unroll
    for (int r = 0; r < 8; r++) {
        int grow = m0 + ty * 8 + r;
        if (grow < M) {
            float o[8];
            #pragma unroll
            for (int c = 0; c < 4; c++) {
                float2 v = unpack2(acc1[r][c]);
                o[2 * c]     = v.x + bv[2 * c];
                o[2 * c + 1] = v.y + bv[2 * c + 1];
            }
            if (relu1) {
                #pragma unroll
                for (int j = 0; j < 8; j++) o[j] = fmaxf(o[j], 0.0f);
            }
            float4* d1 = (float4*)(out1 + (size_t)grow * 128 + tx * 8);
            d1[0] = make_float4(o[0], o[1], o[2], o[3]);
            d1[1] = make_float4(o[4], o[5], o[6], o[7]);
            if (DUAL) {
                float p[8];
                #pragma unroll
                for (int c = 0; c < 4; c++) {
                    float2 v = unpack2(acc2[r][c]);
                    p[2 * c]     = v.x;
                    p[2 * c + 1] = v.y;
                }
                float4* d2 = (float4*)(out2 + (size_t)grow * 128 + tx * 8);
                d2[0] = make_float4(p[0], p[1], p[2], p[3]);
                d2[1] = make_float4(p[4], p[5], p[6], p[7]);
            }
        }
    }
}

// ---------------- CSR build ----------------
__global__ void zero_kernel() {
    int i = blockIdx.x * blockDim.x + threadIdx.x;
    if (i < N_NODES) g_cnt[i] = 0;
    if (i < N_GRAPHS * HID) g_gsum[i] = 0.0f;
    if (i < N_GRAPHS) g_gcnt[i] = 0.0f;
}

__global__ void hist_kernel(const int* __restrict__ dst) {
    int e4 = blockIdx.x * blockDim.x + threadIdx.x;
    if (e4 < N_EDGES / 4) {
        int4 d = ((const int4*)dst)[e4];
        atomicAdd(&g_cnt[d.x], 1);
        atomicAdd(&g_cnt[d.y], 1);
        atomicAdd(&g_cnt[d.z], 1);
        atomicAdd(&g_cnt[d.w], 1);
    }
}

// level-1: per-block sums of g_cnt
__global__ void scan1_kernel() {
    __shared__ int ws[8];
    int tid = threadIdx.x, lane = tid & 31, w = tid >> 5;
    int i = blockIdx.x * 256 + tid;
    int v = (i < N_NODES) ? g_cnt[i] : 0;
    #pragma unroll
    for (int off = 16; off > 0; off >>= 1)
        v += __shfl_down_sync(0xffffffffu, v, off);
    if (lane == 0) ws[w] = v;
    __syncthreads();
    if (tid == 0) {
        int s = 0;
        #pragma unroll
        for (int j = 0; j < 8; j++) s += ws[j];
        g_bsum[blockIdx.x] = s;
    }
}

// level-2+3 merged: every block redundantly scans the 196 block sums
// to get its own offset, then scans its 256-element slice of g_cnt.
__global__ void scan3m_kernel() {
    __shared__ int ws[8];
    __shared__ int s_boff;
    int tid = threadIdx.x, lane = tid & 31, w = tid >> 5;

    // phase A: exclusive prefix of g_bsum at index blockIdx.x
    int v = (tid < SCAN_BLOCKS) ? g_bsum[tid] : 0;
    int x = v;
    #pragma unroll
    for (int off = 1; off < 32; off <<= 1) {
        int t = __shfl_up_sync(0xffffffffu, x, off);
        if (lane >= off) x += t;
    }
    if (lane == 31) ws[w] = x;
    __syncthreads();
    if (w == 0 && lane < 8) {
        int y = ws[lane];
        #pragma unroll
        for (int off = 1; off < 8; off <<= 1) {
            int t = __shfl_up_sync(0xffu, y, off);
            if (lane >= off) y += t;
        }
        ws[lane] = y;
    }
    __syncthreads();
    int incl = x + (w > 0 ? ws[w - 1] : 0);
    if (tid == blockIdx.x) s_boff = incl - v;
    if (blockIdx.x == 0 && tid == 0) g_rowptr[0] = 0;
    __syncthreads();

    // phase B: scan this block's slice of g_cnt
    int i = blockIdx.x * 256 + tid;
    int c = (i < N_NODES) ? g_cnt[i] : 0;
    int y = c;
    #pragma unroll
    for (int off = 1; off < 32; off <<= 1) {
        int t = __shfl_up_sync(0xffffffffu, y, off);
        if (lane >= off) y += t;
    }
    if (lane == 31) ws[w] = y;
    __syncthreads();
    if (w == 0 && lane < 8) {
        int z = ws[lane];
        #pragma unroll
        for (int off = 1; off < 8; off <<= 1) {
            int t = __shfl_up_sync(0xffu, z, off);
            if (lane >= off) z += t;
        }
        ws[lane] = z;
    }
    __syncthreads();
    int inc2 = y + (w > 0 ? ws[w - 1] : 0) + s_boff;
    if (i < N_NODES) {
        g_rowptr[i + 1] = inc2;
        g_cursor[i] = inc2 - c;
    }
}

__global__ void fill_kernel(const int* __restrict__ src,
                            const int* __restrict__ dst) {
    int e4 = blockIdx.x * blockDim.x + threadIdx.x;
    if (e4 < N_EDGES / 4) {
        int4 d = ((const int4*)dst)[e4];
        int4 s = ((const int4*)src)[e4];
        g_col[atomicAdd(&g_cursor[d.x], 1)] = s.x;
        g_col[atomicAdd(&g_cursor[d.y], 1)] = s.y;
        g_col[atomicAdd(&g_cursor[d.z], 1)] = s.z;
        g_col[atomicAdd(&g_cursor[d.w], 1)] = s.w;
    }
}

// ------- fused aggregation: out = relu(partial + mean_{j in N(i)} P_j) -------
// warp per node, float4 per lane
__global__ void aggf_kernel(const float* __restrict__ P,
                            const float* __restrict__ partial,
                            float* __restrict__ out) {
    int node = (blockIdx.x * blockDim.x + threadIdx.x) >> 5;
    int lane = threadIdx.x & 31;
    if (node >= N_NODES) return;
    int s = g_rowptr[node];
    int e = g_rowptr[node + 1];
    float4 acc = make_float4(0.f, 0.f, 0.f, 0.f);
    for (int j = s; j < e; j++) {
        int sn = g_col[j];
        float4 v = *(const float4*)(P + (size_t)sn * HID + lane * 4);
        acc.x += v.x; acc.y += v.y; acc.z += v.z; acc.w += v.w;
    }
    int deg = e - s;
    float inv = 1.0f / (float)(deg > 0 ? deg : 1);
    float4 p = *(const float4*)(partial + (size_t)node * HID + lane * 4);
    float4 o;
    o.x = fmaxf(p.x + acc.x * inv, 0.f);
    o.y = fmaxf(p.y + acc.y * inv, 0.f);
    o.z = fmaxf(p.z + acc.z * inv, 0.f);
    o.w = fmaxf(p.w + acc.w * inv, 0.f);
    *(float4*)(out + (size_t)node * HID + lane * 4) = o;
}

// ---------------- pooling (batch is sorted) ----------------
__global__ void pool_kernel(const float* __restrict__ h,
                            const int* __restrict__ batch) {
    int t = threadIdx.x;
    int r0 = blockIdx.x * 128;
    if (r0 >= N_NODES) return;
    int r1 = r0 + 128; if (r1 > N_NODES) r1 = N_NODES;
    int gprev = batch[r0];
    float acc = 0.0f;
    float cacc = 0.0f;
    for (int r = r0; r < r1; r++) {
        int g = batch[r];
        if (g != gprev) {
            atomicAdd(&g_gsum[gprev * HID + t], acc);
            if (t == 0) atomicAdd(&g_gcnt[gprev], cacc);
            acc = 0.0f; cacc = 0.0f; gprev = g;
        }
        acc += h[(size_t)r * HID + t];
        cacc += 1.0f;
    }
    atomicAdd(&g_gsum[gprev * HID + t], acc);
    if (t == 0) atomicAdd(&g_gcnt[gprev], cacc);
}

// ---------------- final: out[g][o] = mean_pool @ fc^T + fc_b ----------------
__global__ void final_kernel(const float* __restrict__ fcW,
                             const float* __restrict__ fcb,
                             float* __restrict__ out) {
    int t = threadIdx.x;
    if (t >= N_GRAPHS * D_OUT) return;
    int g = t / D_OUT, o = t % D_OUT;
    float cnt = g_gcnt[g];
    float inv = 1.0f / fmaxf(cnt, 1.0f);
    float s = 0.0f;
    #pragma unroll 8
    for (int k = 0; k < HID; k++)
        s += g_gsum[g * HID + k] * fcW[o * HID + k];
    out[g * D_OUT + o] = s * inv + fcb[o];
}

// ---------------- launch ----------------
extern "C" void kernel_launch(void* const* d_in, const int* in_sizes, int n_in,
                              void* d_out, int out_size) {
    const float* x    = (const float*)d_in[0];
    const float* Wl0  = (const float*)d_in[1];
    const float* bl0  = (const float*)d_in[2];
    const float* Wr0  = (const float*)d_in[3];
    const float* W1   = (const float*)d_in[4];
    const float* b1   = (const float*)d_in[5];
    const float* Wl1  = (const float*)d_in[6];
    const float* bl1  = (const float*)d_in[7];
    const float* Wr1  = (const float*)d_in[8];
    const float* fcW  = (const float*)d_in[9];
    const float* fcb  = (const float*)d_in[10];
    const int*   ei   = (const int*)d_in[11];     // int64 ref -> int32 harness
    const int*   batch= (const int*)d_in[12];
    float*       out  = (float*)d_out;

    const int* src = ei;
    const int* dst = ei + N_EDGES;

    void *pAg = nullptr, *pA = nullptr, *pB = nullptr;
    cudaGetSymbolAddress(&pAg, g_aggr);
    cudaGetSymbolAddress(&pA,  g_bufA);
    cudaGetSymbolAddress(&pB,  g_bufB);
    float* P    = (float*)pAg;
    float* bufA = (float*)pA;
    float* bufB = (float*)pB;

    const int SMEM_D = 3 * 16384 * sizeof(float);   // 196608 (dual)
    const int SMEM_S = 2 * 16384 * sizeof(float);   // 131072 (single)
    cudaFuncSetAttribute(gemm_dw<1>, cudaFuncAttributeMaxDynamicSharedMemorySize, SMEM_D);
    cudaFuncSetAttribute(gemm_dw<0>, cudaFuncAttributeMaxDynamicSharedMemorySize, SMEM_S);

    int gemm_blocks = (N_NODES + 127) / 128;   // 391

    // CSR build
    zero_kernel<<<(N_NODES + 255) / 256, 256>>>();
    hist_kernel<<<(N_EDGES / 4 + 255) / 256, 256>>>(dst);
    scan1_kernel<<<SCAN_BLOCKS, 256>>>();
    scan3m_kernel<<<SCAN_BLOCKS, 256>>>();
    fill_kernel<<<(N_EDGES / 4 + 255) / 256, 256>>>(src, dst);

    // conv0: partial = x@Wr0^T + bl0 (bufA), P = x@Wl0^T;  bufB = relu(partial + agg(P))
    gemm_dw<1><<<gemm_blocks, 256, SMEM_D>>>(x, Wr0, Wl0, bl0, bufA, P, N_NODES, 0);
    aggf_kernel<<<(N_NODES + 7) / 8, 256>>>(P, bufA, bufB);

    // lin1: bufA = relu(bufB@W1^T + b1)
    gemm_dw<0><<<gemm_blocks, 256, SMEM_S>>>(bufB, W1, nullptr, b1, bufA, nullptr, N_NODES, 1);

    // conv1: partial = bufA@Wr1^T + bl1 (bufB), P = bufA@Wl1^T;  bufA = relu(partial + agg(P))
    gemm_dw<1><<<gemm_blocks, 256, SMEM_D>>>(bufA, Wr1, Wl1, bl1, bufB, P, N_NODES, 0);
    aggf_kernel<<<(N_NODES + 7) / 8, 256>>>(P, bufB, bufA);

    // pool + fc
    pool_kernel<<<(N_NODES + 127) / 128, 128>>>(bufA, batch);
    final_kernel<<<1, 96>>>(fcW, fcb, out);
}

// round 6
// speedup vs baseline: 1.3525x; 1.0993x over previous
#include <cuda_runtime.h>
#include <cuda_bf16.h>
#include <cstdint>

#define N_NODES 50000
#define N_EDGES 600000
#define HID     128
#define N_GRAPHS 32
#define D_OUT   3
#define SCAN_BLOCKS ((N_NODES + 255) / 256)   // 196

typedef unsigned long long u64;

// ---------------- scratch (device globals; no allocs) ----------------
__device__ int   g_cnt[N_NODES];
__device__ int   g_rowptr[N_NODES + 1];
__device__ int   g_cursor[N_NODES];
__device__ int   g_col[N_EDGES];
__device__ int   g_bsum[SCAN_BLOCKS];
__device__ __nv_bfloat16 g_P[(size_t)N_NODES * HID];   // messages, bf16
__device__ float g_bufA[(size_t)N_NODES * HID];
__device__ float g_bufB[(size_t)N_NODES * HID];
__device__ float g_gsum[N_GRAPHS * HID];
__device__ float g_gcnt[N_GRAPHS];

// ---------------- f32x2 helpers ----------------
__device__ __forceinline__ u64 pack_dup(float a) {
    u64 r;
    asm("mov.b64 %0, {%1,%1};" : "=l"(r) : "f"(a));
    return r;
}
__device__ __forceinline__ float2 unpack2(u64 v) {
    float2 r;
    asm("mov.b64 {%0,%1}, %2;" : "=f"(r.x), "=f"(r.y) : "l"(v));
    return r;
}
__device__ __forceinline__ void ffma2(u64& acc, u64 a, u64 b) {
    asm("fma.rn.f32x2 %0, %1, %2, %0;" : "+l"(acc) : "l"(a), "l"(b));
}

// =================================================================
// Dual-weight GEMM: out1 = A@W1^T + bias (relu opt) [fp32]
//                   out2 = A@W2^T                   [bf16]
// 128x128 block tile, 256 threads, 8x8 microtile, packed fma.rn.f32x2.
// =================================================================
template<int DUAL>
__global__ void __launch_bounds__(256, 1)
gemm_dw(const float* __restrict__ A,
        const float* __restrict__ W1, const float* __restrict__ W2,
        const float* __restrict__ bias,
        float* __restrict__ out1, __nv_bfloat16* __restrict__ out2,
        int M, int relu1) {
    extern __shared__ float smem[];
    float* sIn = smem;            // [row*128 + k]
    float* sW1 = smem + 16384;    // k-major, float4 XOR-swizzled along cols
    float* sW2 = smem + 32768;

    int tid = threadIdx.x;
    int tx = tid & 15;        // col group (8 cols)
    int ty = tid >> 4;        // row group (8 rows)
    int m0 = blockIdx.x * 128;
    int lane = tid & 31;
    int sub  = tid >> 5;      // 0..7

    // load input tile [128 rows x 128 k]
    #pragma unroll
    for (int it = 0; it < 16; it++) {
        int row = it * 8 + sub;
        int grow = m0 + row;
        float4 v = make_float4(0.f, 0.f, 0.f, 0.f);
        if (grow < M) v = *(const float4*)(A + (size_t)grow * 128 + lane * 4);
        *(float4*)(sIn + row * 128 + lane * 4) = v;
    }
    // load W transposed into k-major with float4 XOR swizzle:
    // logical (k, c4) lives at sW[k*128 + ((c4 ^ ((k>>2)&31))<<2)]
    #pragma unroll
    for (int it = 0; it < 16; it++) {
        int col = it * 8 + sub;
        float4 v1 = *(const float4*)(W1 + col * 128 + (lane << 2));
        int c4 = col >> 2;
        int cl = col & 3;
        float vv1[4] = {v1.x, v1.y, v1.z, v1.w};
        #pragma unroll
        for (int i = 0; i < 4; i++) {
            int k = (lane << 2) + i;     // (k>>2)&31 == lane
            sW1[k * 128 + ((c4 ^ lane) << 2) + cl] = vv1[i];
        }
        if (DUAL) {
            float4 v2 = *(const float4*)(W2 + col * 128 + (lane << 2));
            float vv2[4] = {v2.x, v2.y, v2.z, v2.w};
            #pragma unroll
            for (int i = 0; i < 4; i++) {
                int k = (lane << 2) + i;
                sW2[k * 128 + ((c4 ^ lane) << 2) + cl] = vv2[i];
            }
        }
    }
    __syncthreads();

    u64 acc1[8][4];
    u64 acc2[DUAL ? 8 : 1][4];
    #pragma unroll
    for (int r = 0; r < 8; r++)
        #pragma unroll
        for (int c = 0; c < 4; c++) acc1[r][c] = 0ull;
    #pragma unroll
    for (int r = 0; r < (DUAL ? 8 : 1); r++)
        #pragma unroll
        for (int c = 0; c < 4; c++) acc2[r][c] = 0ull;

    #pragma unroll 4
    for (int k = 0; k < 128; k++) {
        u64 a2[8];
        #pragma unroll
        for (int r = 0; r < 8; r++)
            a2[r] = pack_dup(sIn[(ty * 8 + r) * 128 + k]);
        int swz = (k >> 2) & 31;
        const float* w1r = sW1 + k * 128;
        ulonglong2 p0 = *(const ulonglong2*)(w1r + ((((tx << 1)    ) ^ swz) << 2));
        ulonglong2 p1 = *(const ulonglong2*)(w1r + ((((tx << 1) | 1) ^ swz) << 2));
        u64 b1[4] = {p0.x, p0.y, p1.x, p1.y};
        #pragma unroll
        for (int r = 0; r < 8; r++)
            #pragma unroll
            for (int c = 0; c < 4; c++)
                ffma2(acc1[r][c], a2[r], b1[c]);
        if (DUAL) {
            const float* w2r = sW2 + k * 128;
            ulonglong2 q0 = *(const ulonglong2*)(w2r + ((((tx << 1)    ) ^ swz) << 2));
            ulonglong2 q1 = *(const ulonglong2*)(w2r + ((((tx << 1) | 1) ^ swz) << 2));
            u64 b2[4] = {q0.x, q0.y, q1.x, q1.y};
            #pragma unroll
            for (int r = 0; r < 8; r++)
                #pragma unroll
                for (int c = 0; c < 4; c++)
                    ffma2(acc2[r][c], a2[r], b2[c]);
        }
    }

    // epilogue
    float bv[8];
    #pragma unroll
    for (int j = 0; j < 8; j++) bv[j] = bias[tx * 8 + j];

    #pragma unroll
    for (int r = 0; r < 8; r++) {
        int grow = m0 + ty * 8 + r;
        if (grow < M) {
            float o[8];
            #pragma unroll
            for (int c = 0; c < 4; c++) {
                float2 v = unpack2(acc1[r][c]);
                o[2 * c]     = v.x + bv[2 * c];
                o[2 * c + 1] = v.y + bv[2 * c + 1];
            }
            if (relu1) {
                #pragma unroll
                for (int j = 0; j < 8; j++) o[j] = fmaxf(o[j], 0.0f);
            }
            float4* d1 = (float4*)(out1 + (size_t)grow * 128 + tx * 8);
            d1[0] = make_float4(o[0], o[1], o[2], o[3]);
            d1[1] = make_float4(o[4], o[5], o[6], o[7]);
            if (DUAL) {
                // P -> bf16 (8 values = 16 bytes)
                __nv_bfloat162 h[4];
                #pragma unroll
                for (int c = 0; c < 4; c++) {
                    float2 v = unpack2(acc2[r][c]);
                    h[c] = __float22bfloat162_rn(v);
                }
                uint4 pk;
                pk.x = *(uint32_t*)&h[0];
                pk.y = *(uint32_t*)&h[1];
                pk.z = *(uint32_t*)&h[2];
                pk.w = *(uint32_t*)&h[3];
                *(uint4*)(out2 + (size_t)grow * 128 + tx * 8) = pk;
            }
        }
    }
}

// ---------------- CSR build ----------------
__global__ void zero_kernel() {
    int i = blockIdx.x * blockDim.x + threadIdx.x;
    if (i < N_NODES) g_cnt[i] = 0;
    if (i < N_GRAPHS * HID) g_gsum[i] = 0.0f;
    if (i < N_GRAPHS) g_gcnt[i] = 0.0f;
}

__global__ void hist_kernel(const int* __restrict__ dst) {
    int e4 = blockIdx.x * blockDim.x + threadIdx.x;
    if (e4 < N_EDGES / 4) {
        int4 d = ((const int4*)dst)[e4];
        atomicAdd(&g_cnt[d.x], 1);
        atomicAdd(&g_cnt[d.y], 1);
        atomicAdd(&g_cnt[d.z], 1);
        atomicAdd(&g_cnt[d.w], 1);
    }
}

// level-1: per-block sums of g_cnt
__global__ void scan1_kernel() {
    __shared__ int ws[8];
    int tid = threadIdx.x, lane = tid & 31, w = tid >> 5;
    int i = blockIdx.x * 256 + tid;
    int v = (i < N_NODES) ? g_cnt[i] : 0;
    #pragma unroll
    for (int off = 16; off > 0; off >>= 1)
        v += __shfl_down_sync(0xffffffffu, v, off);
    if (lane == 0) ws[w] = v;
    __syncthreads();
    if (tid == 0) {
        int s = 0;
        #pragma unroll
        for (int j = 0; j < 8; j++) s += ws[j];
        g_bsum[blockIdx.x] = s;
    }
}

// level-2+3 merged: every block redundantly scans the 196 block sums
// to get its own offset, then scans its 256-element slice of g_cnt.
__global__ void scan3m_kernel() {
    __shared__ int ws[8];
    __shared__ int s_boff;
    int tid = threadIdx.x, lane = tid & 31, w = tid >> 5;

    // phase A: exclusive prefix of g_bsum at index blockIdx.x
    int v = (tid < SCAN_BLOCKS) ? g_bsum[tid] : 0;
    int x = v;
    #pragma unroll
    for (int off = 1; off < 32; off <<= 1) {
        int t = __shfl_up_sync(0xffffffffu, x, off);
        if (lane >= off) x += t;
    }
    if (lane == 31) ws[w] = x;
    __syncthreads();
    if (w == 0 && lane < 8) {
        int y = ws[lane];
        #pragma unroll
        for (int off = 1; off < 8; off <<= 1) {
            int t = __shfl_up_sync(0xffu, y, off);
            if (lane >= off) y += t;
        }
        ws[lane] = y;
    }
    __syncthreads();
    int incl = x + (w > 0 ? ws[w - 1] : 0);
    if (tid == blockIdx.x) s_boff = incl - v;
    if (blockIdx.x == 0 && tid == 0) g_rowptr[0] = 0;
    __syncthreads();

    // phase B: scan this block's slice of g_cnt
    int i = blockIdx.x * 256 + tid;
    int c = (i < N_NODES) ? g_cnt[i] : 0;
    int y = c;
    #pragma unroll
    for (int off = 1; off < 32; off <<= 1) {
        int t = __shfl_up_sync(0xffffffffu, y, off);
        if (lane >= off) y += t;
    }
    if (lane == 31) ws[w] = y;
    __syncthreads();
    if (w == 0 && lane < 8) {
        int z = ws[lane];
        #pragma unroll
        for (int off = 1; off < 8; off <<= 1) {
            int t = __shfl_up_sync(0xffu, z, off);
            if (lane >= off) z += t;
        }
        ws[lane] = z;
    }
    __syncthreads();
    int inc2 = y + (w > 0 ? ws[w - 1] : 0) + s_boff;
    if (i < N_NODES) {
        g_rowptr[i + 1] = inc2;
        g_cursor[i] = inc2 - c;
    }
}

__global__ void fill_kernel(const int* __restrict__ src,
                            const int* __restrict__ dst) {
    int e4 = blockIdx.x * blockDim.x + threadIdx.x;
    if (e4 < N_EDGES / 4) {
        int4 d = ((const int4*)dst)[e4];
        int4 s = ((const int4*)src)[e4];
        g_col[atomicAdd(&g_cursor[d.x], 1)] = s.x;
        g_col[atomicAdd(&g_cursor[d.y], 1)] = s.y;
        g_col[atomicAdd(&g_cursor[d.z], 1)] = s.z;
        g_col[atomicAdd(&g_cursor[d.w], 1)] = s.w;
    }
}

// ------- fused aggregation: out = relu(partial + mean_{j in N(i)} P_j) -------
// warp per node; P is bf16 (256B rows): lane loads uint2 = 4 bf16.
__global__ void aggf_kernel(const __nv_bfloat16* __restrict__ P,
                            const float* __restrict__ partial,
                            float* __restrict__ out) {
    int node = (blockIdx.x * blockDim.x + threadIdx.x) >> 5;
    int lane = threadIdx.x & 31;
    if (node >= N_NODES) return;
    int s = g_rowptr[node];
    int e = g_rowptr[node + 1];
    float4 acc = make_float4(0.f, 0.f, 0.f, 0.f);
    for (int j = s; j < e; j++) {
        int sn = g_col[j];
        uint2 v = *((const uint2*)(P + (size_t)sn * HID) + lane);
        float2 f0 = __bfloat1622float2(*reinterpret_cast<__nv_bfloat162*>(&v.x));
        float2 f1 = __bfloat1622float2(*reinterpret_cast<__nv_bfloat162*>(&v.y));
        acc.x += f0.x; acc.y += f0.y; acc.z += f1.x; acc.w += f1.y;
    }
    int deg = e - s;
    float inv = 1.0f / (float)(deg > 0 ? deg : 1);
    float4 p = *(const float4*)(partial + (size_t)node * HID + lane * 4);
    float4 o;
    o.x = fmaxf(p.x + acc.x * inv, 0.f);
    o.y = fmaxf(p.y + acc.y * inv, 0.f);
    o.z = fmaxf(p.z + acc.z * inv, 0.f);
    o.w = fmaxf(p.w + acc.w * inv, 0.f);
    *(float4*)(out + (size_t)node * HID + lane * 4) = o;
}

// ---------------- pooling (batch is sorted) ----------------
__global__ void pool_kernel(const float* __restrict__ h,
                            const int* __restrict__ batch) {
    int t = threadIdx.x;
    int r0 = blockIdx.x * 128;
    if (r0 >= N_NODES) return;
    int r1 = r0 + 128; if (r1 > N_NODES) r1 = N_NODES;
    int gprev = batch[r0];
    float acc = 0.0f;
    float cacc = 0.0f;
    for (int r = r0; r < r1; r++) {
        int g = batch[r];
        if (g != gprev) {
            atomicAdd(&g_gsum[gprev * HID + t], acc);
            if (t == 0) atomicAdd(&g_gcnt[gprev], cacc);
            acc = 0.0f; cacc = 0.0f; gprev = g;
        }
        acc += h[(size_t)r * HID + t];
        cacc += 1.0f;
    }
    atomicAdd(&g_gsum[gprev * HID + t], acc);
    if (t == 0) atomicAdd(&g_gcnt[gprev], cacc);
}

// ---------------- final: out[g][o] = mean_pool @ fc^T + fc_b ----------------
__global__ void final_kernel(const float* __restrict__ fcW,
                             const float* __restrict__ fcb,
                             float* __restrict__ out) {
    int t = threadIdx.x;
    if (t >= N_GRAPHS * D_OUT) return;
    int g = t / D_OUT, o = t % D_OUT;
    float cnt = g_gcnt[g];
    float inv = 1.0f / fmaxf(cnt, 1.0f);
    float s = 0.0f;
    #pragma unroll 8
    for (int k = 0; k < HID; k++)
        s += g_gsum[g * HID + k] * fcW[o * HID + k];
    out[g * D_OUT + o] = s * inv + fcb[o];
}

// ---------------- launch ----------------
extern "C" void kernel_launch(void* const* d_in, const int* in_sizes, int n_in,
                              void* d_out, int out_size) {
    const float* x    = (const float*)d_in[0];
    const float* Wl0  = (const float*)d_in[1];
    const float* bl0  = (const float*)d_in[2];
    const float* Wr0  = (const float*)d_in[3];
    const float* W1   = (const float*)d_in[4];
    const float* b1   = (const float*)d_in[5];
    const float* Wl1  = (const float*)d_in[6];
    const float* bl1  = (const float*)d_in[7];
    const float* Wr1  = (const float*)d_in[8];
    const float* fcW  = (const float*)d_in[9];
    const float* fcb  = (const float*)d_in[10];
    const int*   ei   = (const int*)d_in[11];     // int64 ref -> int32 harness
    const int*   batch= (const int*)d_in[12];
    float*       out  = (float*)d_out;

    const int* src = ei;
    const int* dst = ei + N_EDGES;

    void *pP = nullptr, *pA = nullptr, *pB = nullptr;
    cudaGetSymbolAddress(&pP, g_P);
    cudaGetSymbolAddress(&pA, g_bufA);
    cudaGetSymbolAddress(&pB, g_bufB);
    __nv_bfloat16* P = (__nv_bfloat16*)pP;
    float* bufA = (float*)pA;
    float* bufB = (float*)pB;

    const int SMEM_D = 3 * 16384 * sizeof(float);   // 196608 (dual)
    const int SMEM_S = 2 * 16384 * sizeof(float);   // 131072 (single)
    cudaFuncSetAttribute(gemm_dw<1>, cudaFuncAttributeMaxDynamicSharedMemorySize, SMEM_D);
    cudaFuncSetAttribute(gemm_dw<0>, cudaFuncAttributeMaxDynamicSharedMemorySize, SMEM_S);

    int gemm_blocks = (N_NODES + 127) / 128;   // 391

    // CSR build
    zero_kernel<<<(N_NODES + 255) / 256, 256>>>();
    hist_kernel<<<(N_EDGES / 4 + 255) / 256, 256>>>(dst);
    scan1_kernel<<<SCAN_BLOCKS, 256>>>();
    scan3m_kernel<<<SCAN_BLOCKS, 256>>>();
    fill_kernel<<<(N_EDGES / 4 + 255) / 256, 256>>>(src, dst);

    // conv0: partial = x@Wr0^T + bl0 (bufA), P = bf16(x@Wl0^T); bufB = relu(partial + agg(P))
    gemm_dw<1><<<gemm_blocks, 256, SMEM_D>>>(x, Wr0, Wl0, bl0, bufA, P, N_NODES, 0);
    aggf_kernel<<<(N_NODES + 7) / 8, 256>>>(P, bufA, bufB);

    // lin1: bufA = relu(bufB@W1^T + b1)
    gemm_dw<0><<<gemm_blocks, 256, SMEM_S>>>(bufB, W1, nullptr, b1, bufA, nullptr, N_NODES, 1);

    // conv1: partial = bufA@Wr1^T + bl1 (bufB), P = bf16(bufA@Wl1^T); bufA = relu(partial + agg(P))
    gemm_dw<1><<<gemm_blocks, 256, SMEM_D>>>(bufA, Wr1, Wl1, bl1, bufB, P, N_NODES, 0);
    aggf_kernel<<<(N_NODES + 7) / 8, 256>>>(P, bufB, bufA);

    // pool + fc
    pool_kernel<<<(N_NODES + 127) / 128, 128>>>(bufA, batch);
    final_kernel<<<1, 96>>>(fcW, fcb, out);
}

// round 7
// speedup vs baseline: 1.4239x; 1.0528x over previous
#include <cuda_runtime.h>
#include <cuda_bf16.h>
#include <cstdint>

#define N_NODES 50000
#define N_EDGES 600000
#define HID     128
#define N_GRAPHS 32
#define D_OUT   3
#define SCAN_BLOCKS ((N_NODES + 255) / 256)   // 196

typedef unsigned long long u64;

// ---------------- scratch (device globals; no allocs) ----------------
__device__ int   g_cnt[N_NODES];
__device__ int   g_rowptr[N_NODES + 1];
__device__ int   g_cursor[N_NODES];
__device__ int   g_col[N_EDGES];
__device__ int   g_bsum[SCAN_BLOCKS];
__device__ __nv_bfloat16 g_P[(size_t)N_NODES * HID];   // messages, bf16
__device__ float g_bufA[(size_t)N_NODES * HID];
__device__ float g_bufB[(size_t)N_NODES * HID];
__device__ float g_gsum[N_GRAPHS * HID];
__device__ float g_gcnt[N_GRAPHS];

// ---------------- f32x2 helpers ----------------
__device__ __forceinline__ u64 pack_dup(float a) {
    u64 r;
    asm("mov.b64 %0, {%1,%1};" : "=l"(r) : "f"(a));
    return r;
}
__device__ __forceinline__ float2 unpack2(u64 v) {
    float2 r;
    asm("mov.b64 {%0,%1}, %2;" : "=f"(r.x), "=f"(r.y) : "l"(v));
    return r;
}
__device__ __forceinline__ void ffma2(u64& acc, u64 a, u64 b) {
    asm("fma.rn.f32x2 %0, %1, %2, %0;" : "+l"(acc) : "l"(a), "l"(b));
}

// =================================================================
// Dual-weight GEMM: out1 = A@W1^T + bias (relu opt) [fp32]
//                   out2 = A@W2^T                   [bf16]
// 128x128 block tile, 256 threads, 8x8 microtile, packed fma.rn.f32x2.
// =================================================================
template<int DUAL>
__global__ void __launch_bounds__(256, 1)
gemm_dw(const float* __restrict__ A,
        const float* __restrict__ W1, const float* __restrict__ W2,
        const float* __restrict__ bias,
        float* __restrict__ out1, __nv_bfloat16* __restrict__ out2,
        int M, int relu1) {
    extern __shared__ float smem[];
    float* sIn = smem;            // [row*128 + k]
    float* sW1 = smem + 16384;    // k-major, float4 XOR-swizzled along cols
    float* sW2 = smem + 32768;

    int tid = threadIdx.x;
    int tx = tid & 15;        // col group (8 cols)
    int ty = tid >> 4;        // row group (8 rows)
    int m0 = blockIdx.x * 128;
    int lane = tid & 31;
    int sub  = tid >> 5;      // 0..7

    // load input tile [128 rows x 128 k]
    #pragma unroll
    for (int it = 0; it < 16; it++) {
        int row = it * 8 + sub;
        int grow = m0 + row;
        float4 v = make_float4(0.f, 0.f, 0.f, 0.f);
        if (grow < M) v = *(const float4*)(A + (size_t)grow * 128 + lane * 4);
        *(float4*)(sIn + row * 128 + lane * 4) = v;
    }
    // load W transposed into k-major with float4 XOR swizzle:
    // logical (k, c4) lives at sW[k*128 + ((c4 ^ ((k>>2)&31))<<2)]
    #pragma unroll
    for (int it = 0; it < 16; it++) {
        int col = it * 8 + sub;
        float4 v1 = *(const float4*)(W1 + col * 128 + (lane << 2));
        int c4 = col >> 2;
        int cl = col & 3;
        float vv1[4] = {v1.x, v1.y, v1.z, v1.w};
        #pragma unroll
        for (int i = 0; i < 4; i++) {
            int k = (lane << 2) + i;     // (k>>2)&31 == lane
            sW1[k * 128 + ((c4 ^ lane) << 2) + cl] = vv1[i];
        }
        if (DUAL) {
            float4 v2 = *(const float4*)(W2 + col * 128 + (lane << 2));
            float vv2[4] = {v2.x, v2.y, v2.z, v2.w};
            #pragma unroll
            for (int i = 0; i < 4; i++) {
                int k = (lane << 2) + i;
                sW2[k * 128 + ((c4 ^ lane) << 2) + cl] = vv2[i];
            }
        }
    }
    __syncthreads();

    u64 acc1[8][4];
    u64 acc2[DUAL ? 8 : 1][4];
    #pragma unroll
    for (int r = 0; r < 8; r++)
        #pragma unroll
        for (int c = 0; c < 4; c++) acc1[r][c] = 0ull;
    #pragma unroll
    for (int r = 0; r < (DUAL ? 8 : 1); r++)
        #pragma unroll
        for (int c = 0; c < 4; c++) acc2[r][c] = 0ull;

    #pragma unroll 4
    for (int k = 0; k < 128; k++) {
        u64 a2[8];
        #pragma unroll
        for (int r = 0; r < 8; r++)
            a2[r] = pack_dup(sIn[(ty * 8 + r) * 128 + k]);
        int swz = (k >> 2) & 31;
        const float* w1r = sW1 + k * 128;
        ulonglong2 p0 = *(const ulonglong2*)(w1r + ((((tx << 1)    ) ^ swz) << 2));
        ulonglong2 p1 = *(const ulonglong2*)(w1r + ((((tx << 1) | 1) ^ swz) << 2));
        u64 b1[4] = {p0.x, p0.y, p1.x, p1.y};
        #pragma unroll
        for (int r = 0; r < 8; r++)
            #pragma unroll
            for (int c = 0; c < 4; c++)
                ffma2(acc1[r][c], a2[r], b1[c]);
        if (DUAL) {
            const float* w2r = sW2 + k * 128;
            ulonglong2 q0 = *(const ulonglong2*)(w2r + ((((tx << 1)    ) ^ swz) << 2));
            ulonglong2 q1 = *(const ulonglong2*)(w2r + ((((tx << 1) | 1) ^ swz) << 2));
            u64 b2[4] = {q0.x, q0.y, q1.x, q1.y};
            #pragma unroll
            for (int r = 0; r < 8; r++)
                #pragma unroll
                for (int c = 0; c < 4; c++)
                    ffma2(acc2[r][c], a2[r], b2[c]);
        }
    }

    // epilogue
    float bv[8];
    #pragma unroll
    for (int j = 0; j < 8; j++) bv[j] = bias[tx * 8 + j];

    #pragma unroll
    for (int r = 0; r < 8; r++) {
        int grow = m0 + ty * 8 + r;
        if (grow < M) {
            float o[8];
            #pragma unroll
            for (int c = 0; c < 4; c++) {
                float2 v = unpack2(acc1[r][c]);
                o[2 * c]     = v.x + bv[2 * c];
                o[2 * c + 1] = v.y + bv[2 * c + 1];
            }
            if (relu1) {
                #pragma unroll
                for (int j = 0; j < 8; j++) o[j] = fmaxf(o[j], 0.0f);
            }
            float4* d1 = (float4*)(out1 + (size_t)grow * 128 + tx * 8);
            d1[0] = make_float4(o[0], o[1], o[2], o[3]);
            d1[1] = make_float4(o[4], o[5], o[6], o[7]);
            if (DUAL) {
                // P -> bf16 (8 values = 16 bytes)
                __nv_bfloat162 h[4];
                #pragma unroll
                for (int c = 0; c < 4; c++) {
                    float2 v = unpack2(acc2[r][c]);
                    h[c] = __float22bfloat162_rn(v);
                }
                uint4 pk;
                pk.x = *(uint32_t*)&h[0];
                pk.y = *(uint32_t*)&h[1];
                pk.z = *(uint32_t*)&h[2];
                pk.w = *(uint32_t*)&h[3];
                *(uint4*)(out2 + (size_t)grow * 128 + tx * 8) = pk;
            }
        }
    }
}

// ---------------- CSR build ----------------
__global__ void zero_kernel() {
    int i = blockIdx.x * blockDim.x + threadIdx.x;
    if (i < N_NODES) g_cnt[i] = 0;
    if (i < N_GRAPHS * HID) g_gsum[i] = 0.0f;
    if (i < N_GRAPHS) g_gcnt[i] = 0.0f;
}

__global__ void hist_kernel(const int* __restrict__ dst) {
    int e4 = blockIdx.x * blockDim.x + threadIdx.x;
    if (e4 < N_EDGES / 4) {
        int4 d = ((const int4*)dst)[e4];
        atomicAdd(&g_cnt[d.x], 1);
        atomicAdd(&g_cnt[d.y], 1);
        atomicAdd(&g_cnt[d.z], 1);
        atomicAdd(&g_cnt[d.w], 1);
    }
}

// level-1: per-block sums of g_cnt
__global__ void scan1_kernel() {
    __shared__ int ws[8];
    int tid = threadIdx.x, lane = tid & 31, w = tid >> 5;
    int i = blockIdx.x * 256 + tid;
    int v = (i < N_NODES) ? g_cnt[i] : 0;
    #pragma unroll
    for (int off = 16; off > 0; off >>= 1)
        v += __shfl_down_sync(0xffffffffu, v, off);
    if (lane == 0) ws[w] = v;
    __syncthreads();
    if (tid == 0) {
        int s = 0;
        #pragma unroll
        for (int j = 0; j < 8; j++) s += ws[j];
        g_bsum[blockIdx.x] = s;
    }
}

// level-2+3 merged: every block redundantly scans the 196 block sums
// to get its own offset, then scans its 256-element slice of g_cnt.
__global__ void scan3m_kernel() {
    __shared__ int ws[8];
    __shared__ int s_boff;
    int tid = threadIdx.x, lane = tid & 31, w = tid >> 5;

    // phase A: exclusive prefix of g_bsum at index blockIdx.x
    int v = (tid < SCAN_BLOCKS) ? g_bsum[tid] : 0;
    int x = v;
    #pragma unroll
    for (int off = 1; off < 32; off <<= 1) {
        int t = __shfl_up_sync(0xffffffffu, x, off);
        if (lane >= off) x += t;
    }
    if (lane == 31) ws[w] = x;
    __syncthreads();
    if (w == 0 && lane < 8) {
        int y = ws[lane];
        #pragma unroll
        for (int off = 1; off < 8; off <<= 1) {
            int t = __shfl_up_sync(0xffu, y, off);
            if (lane >= off) y += t;
        }
        ws[lane] = y;
    }
    __syncthreads();
    int incl = x + (w > 0 ? ws[w - 1] : 0);
    if (tid == blockIdx.x) s_boff = incl - v;
    if (blockIdx.x == 0 && tid == 0) g_rowptr[0] = 0;
    __syncthreads();

    // phase B: scan this block's slice of g_cnt
    int i = blockIdx.x * 256 + tid;
    int c = (i < N_NODES) ? g_cnt[i] : 0;
    int y = c;
    #pragma unroll
    for (int off = 1; off < 32; off <<= 1) {
        int t = __shfl_up_sync(0xffffffffu, y, off);
        if (lane >= off) y += t;
    }
    if (lane == 31) ws[w] = y;
    __syncthreads();
    if (w == 0 && lane < 8) {
        int z = ws[lane];
        #pragma unroll
        for (int off = 1; off < 8; off <<= 1) {
            int t = __shfl_up_sync(0xffu, z, off);
            if (lane >= off) z += t;
        }
        ws[lane] = z;
    }
    __syncthreads();
    int inc2 = y + (w > 0 ? ws[w - 1] : 0) + s_boff;
    if (i < N_NODES) {
        g_rowptr[i + 1] = inc2;
        g_cursor[i] = inc2 - c;
    }
}

__global__ void fill_kernel(const int* __restrict__ src,
                            const int* __restrict__ dst) {
    int e4 = blockIdx.x * blockDim.x + threadIdx.x;
    if (e4 < N_EDGES / 4) {
        int4 d = ((const int4*)dst)[e4];
        int4 s = ((const int4*)src)[e4];
        g_col[atomicAdd(&g_cursor[d.x], 1)] = s.x;
        g_col[atomicAdd(&g_cursor[d.y], 1)] = s.y;
        g_col[atomicAdd(&g_cursor[d.z], 1)] = s.z;
        g_col[atomicAdd(&g_cursor[d.w], 1)] = s.w;
    }
}

// ------- fused aggregation: out = relu(partial + mean_{j in N(i)} P_j) -------
// warp per node; P is bf16 (256B rows): lane loads uint2 = 4 bf16.
__global__ void aggf_kernel(const __nv_bfloat16* __restrict__ P,
                            const float* __restrict__ partial,
                            float* __restrict__ out) {
    int node = (blockIdx.x * blockDim.x + threadIdx.x) >> 5;
    int lane = threadIdx.x & 31;
    if (node >= N_NODES) return;
    int s = g_rowptr[node];
    int e = g_rowptr[node + 1];
    float4 acc = make_float4(0.f, 0.f, 0.f, 0.f);
    for (int j = s; j < e; j++) {
        int sn = g_col[j];
        uint2 v = *((const uint2*)(P + (size_t)sn * HID) + lane);
        float2 f0 = __bfloat1622float2(*reinterpret_cast<__nv_bfloat162*>(&v.x));
        float2 f1 = __bfloat1622float2(*reinterpret_cast<__nv_bfloat162*>(&v.y));
        acc.x += f0.x; acc.y += f0.y; acc.z += f1.x; acc.w += f1.y;
    }
    int deg = e - s;
    float inv = 1.0f / (float)(deg > 0 ? deg : 1);
    float4 p = *(const float4*)(partial + (size_t)node * HID + lane * 4);
    float4 o;
    o.x = fmaxf(p.x + acc.x * inv, 0.f);
    o.y = fmaxf(p.y + acc.y * inv, 0.f);
    o.z = fmaxf(p.z + acc.z * inv, 0.f);
    o.w = fmaxf(p.w + acc.w * inv, 0.f);
    *(float4*)(out + (size_t)node * HID + lane * 4) = o;
}

// ---------------- pooling (batch is sorted) ----------------
__global__ void pool_kernel(const float* __restrict__ h,
                            const int* __restrict__ batch) {
    int t = threadIdx.x;
    int r0 = blockIdx.x * 128;
    if (r0 >= N_NODES) return;
    int r1 = r0 + 128; if (r1 > N_NODES) r1 = N_NODES;
    int gprev = batch[r0];
    float acc = 0.0f;
    float cacc = 0.0f;
    for (int r = r0; r < r1; r++) {
        int g = batch[r];
        if (g != gprev) {
            atomicAdd(&g_gsum[gprev * HID + t], acc);
            if (t == 0) atomicAdd(&g_gcnt[gprev], cacc);
            acc = 0.0f; cacc = 0.0f; gprev = g;
        }
        acc += h[(size_t)r * HID + t];
        cacc += 1.0f;
    }
    atomicAdd(&g_gsum[gprev * HID + t], acc);
    if (t == 0) atomicAdd(&g_gcnt[gprev], cacc);
}

// ---------------- final: out[g][o] = mean_pool @ fc^T + fc_b ----------------
__global__ void final_kernel(const float* __restrict__ fcW,
                             const float* __restrict__ fcb,
                             float* __restrict__ out) {
    int t = threadIdx.x;
    if (t >= N_GRAPHS * D_OUT) return;
    int g = t / D_OUT, o = t % D_OUT;
    float cnt = g_gcnt[g];
    float inv = 1.0f / fmaxf(cnt, 1.0f);
    float s = 0.0f;
    #pragma unroll 8
    for (int k = 0; k < HID; k++)
        s += g_gsum[g * HID + k] * fcW[o * HID + k];
    out[g * D_OUT + o] = s * inv + fcb[o];
}

// ---------------- launch ----------------
extern "C" void kernel_launch(void* const* d_in, const int* in_sizes, int n_in,
                              void* d_out, int out_size) {
    const float* x    = (const float*)d_in[0];
    const float* Wl0  = (const float*)d_in[1];
    const float* bl0  = (const float*)d_in[2];
    const float* Wr0  = (const float*)d_in[3];
    const float* W1   = (const float*)d_in[4];
    const float* b1   = (const float*)d_in[5];
    const float* Wl1  = (const float*)d_in[6];
    const float* bl1  = (const float*)d_in[7];
    const float* Wr1  = (const float*)d_in[8];
    const float* fcW  = (const float*)d_in[9];
    const float* fcb  = (const float*)d_in[10];
    const int*   ei   = (const int*)d_in[11];     // int64 ref -> int32 harness
    const int*   batch= (const int*)d_in[12];
    float*       out  = (float*)d_out;

    const int* src = ei;
    const int* dst = ei + N_EDGES;

    void *pP = nullptr, *pA = nullptr, *pB = nullptr;
    cudaGetSymbolAddress(&pP, g_P);
    cudaGetSymbolAddress(&pA, g_bufA);
    cudaGetSymbolAddress(&pB, g_bufB);
    __nv_bfloat16* P = (__nv_bfloat16*)pP;
    float* bufA = (float*)pA;
    float* bufB = (float*)pB;

    const int SMEM_D = 3 * 16384 * sizeof(float);   // 196608 (dual)
    const int SMEM_S = 2 * 16384 * sizeof(float);   // 131072 (single)
    cudaFuncSetAttribute(gemm_dw<1>, cudaFuncAttributeMaxDynamicSharedMemorySize, SMEM_D);
    cudaFuncSetAttribute(gemm_dw<0>, cudaFuncAttributeMaxDynamicSharedMemorySize, SMEM_S);

    // side stream + events, created ONCE on first (non-captured) call
    static cudaStream_t s2 = nullptr;
    static cudaEvent_t evFork = nullptr, evJoin = nullptr;
    if (s2 == nullptr) {
        cudaStreamCreateWithFlags(&s2, cudaStreamNonBlocking);
        cudaEventCreateWithFlags(&evFork, cudaEventDisableTiming);
        cudaEventCreateWithFlags(&evJoin, cudaEventDisableTiming);
    }

    int gemm_blocks = (N_NODES + 127) / 128;   // 391

    // fork: CSR build on s2, conv0 dual GEMM on main stream (independent)
    cudaEventRecord(evFork, 0);
    cudaStreamWaitEvent(s2, evFork, 0);

    zero_kernel<<<(N_NODES + 255) / 256, 256, 0, s2>>>();
    hist_kernel<<<(N_EDGES / 4 + 255) / 256, 256, 0, s2>>>(dst);
    scan1_kernel<<<SCAN_BLOCKS, 256, 0, s2>>>();

    // conv0 on main stream (submission position 4 for ncu)
    gemm_dw<1><<<gemm_blocks, 256, SMEM_D>>>(x, Wr0, Wl0, bl0, bufA, P, N_NODES, 0);

    scan3m_kernel<<<SCAN_BLOCKS, 256, 0, s2>>>();
    fill_kernel<<<(N_EDGES / 4 + 255) / 256, 256, 0, s2>>>(src, dst);

    // join: aggf needs CSR + conv0 outputs
    cudaEventRecord(evJoin, s2);
    cudaStreamWaitEvent(0, evJoin, 0);

    // conv0 combine: bufB = relu(partial + agg(P))
    aggf_kernel<<<(N_NODES + 7) / 8, 256>>>(P, bufA, bufB);

    // lin1: bufA = relu(bufB@W1^T + b1)
    gemm_dw<0><<<gemm_blocks, 256, SMEM_S>>>(bufB, W1, nullptr, b1, bufA, nullptr, N_NODES, 1);

    // conv1: partial = bufA@Wr1^T + bl1 (bufB), P = bf16(bufA@Wl1^T)
    gemm_dw<1><<<gemm_blocks, 256, SMEM_D>>>(bufA, Wr1, Wl1, bl1, bufB, P, N_NODES, 0);
    aggf_kernel<<<(N_NODES + 7) / 8, 256>>>(P, bufB, bufA);

    // pool + fc
    pool_kernel<<<(N_NODES + 127) / 128, 128>>>(bufA, batch);
    final_kernel<<<1, 96>>>(fcW, fcb, out);
}